// round 2
// baseline (speedup 1.0000x reference)
#include <cuda_runtime.h>
#include <math.h>

// Problem constants (b=2,h=8,n=4096,d=64,m=256)
#define BHN   16
#define NSEQ  4096
#define DDIM  64
#define MDIM  256
#define LCOND 256
#define NCHUNK 128
#define LCH   30
#define EDIM  64
#define NSLOT 129         // cond(0) + 128 causal chunks

#define NORMALIZER 0.35355339059327373f  // 64^-0.25
#define DIAGC      0.0625f               // 0.5 * normalizer^2
#define RATIO      0.0625f               // 256^-0.5
#define EPSK       1e-4f
#define EPSC       1e-6f

// ---------------- scratch (static device globals; allocation-free) -----------
__device__ float g_QP[(size_t)BHN * NSEQ * MDIM];            // 64 MB
__device__ float g_KP[(size_t)BHN * NSEQ * MDIM];            // 64 MB
__device__ unsigned g_kmax;
__device__ float g_Lk  [(size_t)BHN * NSLOT * MDIM];
__device__ float g_Lctx[(size_t)BHN * NSLOT * MDIM * EDIM];  // 135 MB

__device__ __forceinline__ unsigned ford(float f) {
    unsigned u = __float_as_uint(f);
    return (u & 0x80000000u) ? ~u : (u | 0x80000000u);
}
__device__ __forceinline__ float fuord(unsigned u) {
    return (u & 0x80000000u) ? __uint_as_float(u ^ 0x80000000u)
                             : __uint_as_float(~u);
}

__global__ void init_kernel() { g_kmax = 0u; }

// ---------------- feature map:  dash = norm * (X @ projT) --------------------
// 256 threads; thread j holds proj row j in registers (64 floats).
// 16 data rows per block staged in smem (pad 68 -> 16B-aligned float4 rows).
template <bool IS_Q>
__global__ __launch_bounds__(256) void feat_kernel(const float* __restrict__ data,
                                                   const float* __restrict__ proj) {
    __shared__ float q_s[16 * 68];      // 4.3 KB
    __shared__ float red[8 * 16];
    __shared__ float diag_s[16];
    __shared__ float rmax_s[16];

    const int tid  = threadIdx.x;
    const int lane = tid & 31, wid = tid >> 5;
    const size_t row0 = (size_t)blockIdx.x * 16;

    // proj row tid -> registers (L1/L2 resident after first blocks)
    float4 p[16];
#pragma unroll
    for (int d4 = 0; d4 < 16; d4++)
        p[d4] = *(const float4*)&proj[tid * 64 + d4 * 4];

    // stage 16 data rows
    for (int idx = tid; idx < 16 * 64; idx += 256) {
        int r = idx >> 6, dd = idx & 63;
        q_s[r * 68 + dd] = data[(row0 + r) * 64 + dd];
    }
    __syncthreads();

    if (tid < 16) {
        float s = 0.f;
        for (int dd = 0; dd < 64; dd++) { float x = q_s[tid * 68 + dd]; s += x * x; }
        diag_s[tid] = s * DIAGC;
    }
    __syncthreads();

    float acc[16];
#pragma unroll
    for (int r = 0; r < 16; r++) acc[r] = 0.f;

#pragma unroll
    for (int d4 = 0; d4 < 16; d4++) {
#pragma unroll
        for (int r = 0; r < 16; r++) {
            float4 qv = *(const float4*)&q_s[r * 68 + d4 * 4];   // LDS.128 broadcast
            acc[r] += qv.x * p[d4].x + qv.y * p[d4].y + qv.z * p[d4].z + qv.w * p[d4].w;
        }
    }
#pragma unroll
    for (int r = 0; r < 16; r++) acc[r] *= NORMALIZER;           // dash

    if (IS_Q) {
#pragma unroll
        for (int r = 0; r < 16; r++) {
            float v = acc[r];
            for (int off = 16; off; off >>= 1)
                v = fmaxf(v, __shfl_xor_sync(0xffffffffu, v, off));
            if (lane == 0) red[wid * 16 + r] = v;
        }
        __syncthreads();
        if (tid < 16) {
            float m = red[tid];
            for (int w = 1; w < 8; w++) m = fmaxf(m, red[w * 16 + tid]);
            rmax_s[tid] = m;
        }
        __syncthreads();
#pragma unroll
        for (int r = 0; r < 16; r++)
            g_QP[(row0 + r) * 256 + tid] =
                RATIO * (expf(acc[r] - diag_s[r] - rmax_s[r]) + EPSK);
    } else {
        float bm = acc[0];
#pragma unroll
        for (int r = 1; r < 16; r++) bm = fmaxf(bm, acc[r]);
        for (int off = 16; off; off >>= 1)
            bm = fmaxf(bm, __shfl_xor_sync(0xffffffffu, bm, off));
        if (lane == 0) red[wid] = bm;
        __syncthreads();
        if (tid == 0) {
            float m = red[0];
            for (int w = 1; w < 8; w++) m = fmaxf(m, red[w]);
            atomicMax(&g_kmax, ford(m));
        }
#pragma unroll
        for (int r = 0; r < 16; r++)
            g_KP[(row0 + r) * 256 + tid] = acc[r] - diag_s[r];
    }
}

// ---------------- finalize kp with global max --------------------------------
__global__ __launch_bounds__(256) void finalize_k_kernel() {
    float gmax = fuord(g_kmax);
    size_t i = ((size_t)blockIdx.x * 256 + threadIdx.x) * 4;
    float4 v = *(float4*)&g_KP[i];
    v.x = RATIO * (expf(v.x - gmax) + EPSK);
    v.y = RATIO * (expf(v.y - gmax) + EPSK);
    v.z = RATIO * (expf(v.z - gmax) + EPSK);
    v.w = RATIO * (expf(v.w - gmax) + EPSK);
    *(float4*)&g_KP[i] = v;
}

// ---------------- per-chunk local sums ---------------------------------------
__global__ __launch_bounds__(256) void chunk_sums_kernel(const float* __restrict__ v) {
    __shared__ float kp_s[32 * 256];   // 32 KB
    __shared__ float v_s[32 * 64];     // 8 KB
    const int tid = threadIdx.x;
    const int slot = blockIdx.x, bh = blockIdx.y;
    const int t0  = slot ? (LCOND + (slot - 1) * LCH) : 0;
    const int len = slot ? LCH : LCOND;

    float acc[64];
#pragma unroll
    for (int e = 0; e < 64; e++) acc[e] = 0.f;
    float sk = 0.f;

    for (int base = 0; base < len; base += 32) {
        int tl = min(32, len - base);
        __syncthreads();
        for (int idx = tid; idx < tl * 256; idx += 256)
            kp_s[idx] = g_KP[((size_t)bh * NSEQ + t0 + base) * 256 + idx];
        for (int idx = tid; idx < tl * 64; idx += 256)
            v_s[idx] = v[((size_t)bh * NSEQ + t0 + base) * 64 + idx];
        __syncthreads();
        for (int tt = 0; tt < tl; tt++) {
            float km = kp_s[tt * 256 + tid];
            sk += km;
#pragma unroll
            for (int e4 = 0; e4 < 16; e4++) {
                float4 vv = *(const float4*)&v_s[tt * 64 + e4 * 4];
                acc[e4 * 4 + 0] += km * vv.x;
                acc[e4 * 4 + 1] += km * vv.y;
                acc[e4 * 4 + 2] += km * vv.z;
                acc[e4 * 4 + 3] += km * vv.w;
            }
        }
    }
    g_Lk[((size_t)bh * NSLOT + slot) * 256 + tid] = sk;
    size_t ob = (((size_t)bh * NSLOT + slot) * 256 + tid) * 64;
#pragma unroll
    for (int e4 = 0; e4 < 16; e4++)
        *(float4*)&g_Lctx[ob + e4 * 4] =
            make_float4(acc[e4 * 4], acc[e4 * 4 + 1], acc[e4 * 4 + 2], acc[e4 * 4 + 3]);
}

// ---------------- exclusive prefix over chunks (in place) --------------------
__global__ __launch_bounds__(256) void prefix_kernel() {
    const int g = blockIdx.x * 256 + threadIdx.x;   // 0..16639
    const int bh = blockIdx.y;
    float* buf; size_t base, stride;
    if (g < 256) { buf = g_Lk;   base = (size_t)bh * NSLOT * 256 + g;            stride = 256; }
    else         { buf = g_Lctx; base = (size_t)bh * NSLOT * 16384 + (g - 256);  stride = 16384; }
    float acc = buf[base];
    for (int c = 1; c < NSLOT; c++) {
        size_t a = base + (size_t)c * stride;
        float t = buf[a];
        buf[a] = acc;
        acc += t;
    }
}

// ---------------- conditioning-prefix output ---------------------------------
__global__ __launch_bounds__(128) void cond_out_kernel(float* __restrict__ out) {
    __shared__ float sden[4];
    const int tid = threadIdx.x;
    const int rl = tid >> 6, e = tid & 63;
    const int lane = tid & 31, wid = tid >> 5;
    const int bh = blockIdx.y;
    const int row = blockIdx.x * 2 + rl;
    const float* qrow = g_QP + ((size_t)bh * NSEQ + row) * 256;
    const float* lk0  = g_Lk   + (size_t)bh * NSLOT * 256;
    const float* ctx0 = g_Lctx + (size_t)bh * NSLOT * 16384;

    float p = 0.f;
    for (int m = e; m < 256; m += 64) p += qrow[m] * lk0[m];
    for (int off = 16; off; off >>= 1) p += __shfl_xor_sync(0xffffffffu, p, off);
    if (lane == 0) sden[wid] = p;
    __syncthreads();
    float den = sden[rl * 2] + sden[rl * 2 + 1];

    float acc = 0.f;
    for (int m4 = 0; m4 < 64; m4++) {
        float4 q4 = *(const float4*)&qrow[m4 * 4];
        acc += q4.x * ctx0[(m4 * 4 + 0) * 64 + e] + q4.y * ctx0[(m4 * 4 + 1) * 64 + e]
             + q4.z * ctx0[(m4 * 4 + 2) * 64 + e] + q4.w * ctx0[(m4 * 4 + 3) * 64 + e];
    }
    out[((size_t)bh * NSEQ + row) * 64 + e] = acc / den;
}

// ---------------- causal chunk output (2 m-tiles, <48KB static smem) ---------
#define QPAD 132   // 132*4 = 528 bytes, 16B-aligned rows -> float4 broadcast OK
#define KPAD 133   // 133 mod 32 = 5, gcd(5,32)=1 -> lane-per-row conflict-free

__global__ __launch_bounds__(256) void causal_out_kernel(const float* __restrict__ v,
                                                         float* __restrict__ out) {
    __shared__ float q_s[LCH * QPAD];   // 15.84 KB
    __shared__ float k_s[LCH * KPAD];   // 15.96 KB
    __shared__ float v_s[LCH * 64];     // 7.5 KB
    __shared__ float A[32 * 32];        // 4 KB
    __shared__ float ck[256];           // 1 KB
    __shared__ float dinv[32];

    const int tid = threadIdx.x, lane = tid & 31, w = tid >> 5;
    const int ci = blockIdx.x, bh = blockIdx.y;
    const int t0 = LCOND + ci * LCH;
    const int slot = ci + 1;

    const float* qb = g_QP + ((size_t)bh * NSEQ + t0) * 256;
    const float* kb = g_KP + ((size_t)bh * NSEQ + t0) * 256;
    const float* vb = v    + ((size_t)bh * NSEQ + t0) * 64;
    const float* ctxc = g_Lctx + ((size_t)bh * NSLOT + slot) * 16384;

    for (int idx = tid; idx < LCH * 64; idx += 256) v_s[idx] = vb[idx];
    ck[tid] = g_Lk[((size_t)bh * NSLOT + slot) * 256 + tid];

    // persistent register accumulators across the 2 m-tiles
    float a0 = 0.f, a1 = 0.f, a2 = 0.f, a3 = 0.f;       // A rows w, w+8, w+16, w+24
    float pden[4] = {0.f, 0.f, 0.f, 0.f};               // den rows w+8r
    const int g = tid >> 6, e = tid & 63;               // ctx layout
    float acc[8];
#pragma unroll
    for (int r = 0; r < 8; r++) acc[r] = 0.f;

    const int klane = (lane < LCH) ? lane : (LCH - 1);  // clamp OOB lanes

    for (int mt = 0; mt < 2; mt++) {
        const int m0 = mt * 128;
        __syncthreads();
        for (int idx = tid; idx < LCH * 128; idx += 256) {
            int i = idx >> 7, ml = idx & 127;
            q_s[i * QPAD + ml] = qb[i * 256 + m0 + ml];
            k_s[i * KPAD + ml] = kb[i * 256 + m0 + ml];
        }
        __syncthreads();

        // ---- A partial: warp w rows {w, w+8, w+16, w+24}, lane = column j
        {
            const float* krow = &k_s[klane * KPAD];
            const int iA = w, iB = w + 8, iC = w + 16, iD = (w + 24 < LCH) ? w + 24 : 0;
#pragma unroll 8
            for (int m4 = 0; m4 < 32; m4++) {
                float k0 = krow[m4 * 4 + 0], k1 = krow[m4 * 4 + 1];
                float k2 = krow[m4 * 4 + 2], k3 = krow[m4 * 4 + 3];
                float4 qA = *(const float4*)&q_s[iA * QPAD + m4 * 4];
                float4 qB = *(const float4*)&q_s[iB * QPAD + m4 * 4];
                float4 qC = *(const float4*)&q_s[iC * QPAD + m4 * 4];
                float4 qD = *(const float4*)&q_s[iD * QPAD + m4 * 4];
                a0 += qA.x * k0 + qA.y * k1 + qA.z * k2 + qA.w * k3;
                a1 += qB.x * k0 + qB.y * k1 + qB.z * k2 + qB.w * k3;
                a2 += qC.x * k0 + qC.y * k1 + qC.z * k2 + qC.w * k3;
                a3 += qD.x * k0 + qD.y * k1 + qD.z * k2 + qD.w * k3;
            }
        }

        // ---- den partial: rows i = w + 8r, lane strides m (conflict-free)
#pragma unroll
        for (int r = 0; r < 4; r++) {
            int i = w + 8 * r;
            if (i < LCH) {
                float p = 0.f;
                for (int ml = lane; ml < 128; ml += 32)
                    p += q_s[i * QPAD + ml] * (ck[m0 + ml] + EPSC);
                pden[r] += p;
            }
        }

        // ---- ctx partial: rows i = g + 4r, column e; carry ctx from gmem
        for (int m4 = 0; m4 < 32; m4++) {
            float c0 = ctxc[(m0 + m4 * 4 + 0) * 64 + e];
            float c1 = ctxc[(m0 + m4 * 4 + 1) * 64 + e];
            float c2 = ctxc[(m0 + m4 * 4 + 2) * 64 + e];
            float c3 = ctxc[(m0 + m4 * 4 + 3) * 64 + e];
#pragma unroll
            for (int r = 0; r < 8; r++) {
                int i = g + 4 * r;
                if (i < LCH) {
                    float4 q4 = *(const float4*)&q_s[i * QPAD + m4 * 4];
                    acc[r] += q4.x * c0 + q4.y * c1 + q4.z * c2 + q4.w * c3;
                }
            }
        }
    }

    // ---- commit A (guard invalid rows/cols)
    if (lane < LCH) {
        A[(w     ) * 32 + lane] = a0;
        A[(w +  8) * 32 + lane] = a1;
        A[(w + 16) * 32 + lane] = a2;
        if (w + 24 < LCH) A[(w + 24) * 32 + lane] = a3;
    }
    __syncthreads();

    // ---- den[i] = pden + sum_{j<=i} A[i][j]
#pragma unroll
    for (int r = 0; r < 4; r++) {
        int i = w + 8 * r;
        if (i < LCH) {
            float p = pden[r];
            if (lane <= i) p += A[i * 32 + lane];
            for (int off = 16; off; off >>= 1) p += __shfl_xor_sync(0xffffffffu, p, off);
            if (lane == 0) dinv[i] = 1.f / p;
        }
    }
    __syncthreads();

    // ---- out
#pragma unroll
    for (int r = 0; r < 8; r++) {
        int i = g + 4 * r;
        if (i >= LCH) continue;
        float o = acc[r];
        for (int j = 0; j <= i; j++) o += A[i * 32 + j] * v_s[j * 64 + e];
        out[((size_t)bh * NSEQ + t0 + i) * 64 + e] = o * dinv[i];
    }
}

// ---------------- launch ------------------------------------------------------
extern "C" void kernel_launch(void* const* d_in, const int* in_sizes, int n_in,
                              void* d_out, int out_size) {
    (void)in_sizes; (void)n_in; (void)out_size;
    const float* q    = (const float*)d_in[0];
    const float* k    = (const float*)d_in[1];
    const float* v    = (const float*)d_in[2];
    const float* proj = (const float*)d_in[3];
    float* out = (float*)d_out;

    init_kernel<<<1, 1>>>();
    feat_kernel<false><<<4096, 256>>>(k, proj);
    feat_kernel<true> <<<4096, 256>>>(q, proj);
    finalize_k_kernel <<<16384, 256>>>();
    chunk_sums_kernel <<<dim3(NSLOT, BHN), 256>>>(v);
    prefix_kernel     <<<dim3(65, BHN), 256>>>();
    cond_out_kernel   <<<dim3(128, BHN), 128>>>(out);
    causal_out_kernel <<<dim3(NCHUNK, BHN), 256>>>(v, out);
}

// round 4
// speedup vs baseline: 1.4887x; 1.4887x over previous
#include <cuda_runtime.h>
#include <math.h>

// Problem constants (b=2,h=8,n=4096,d=64,m=256)
#define BHN   16
#define NSEQ  4096
#define DDIM  64
#define MDIM  256
#define LCOND 256
#define NCHUNK 128
#define LCH   30
#define EDIM  64
#define NSLOT 129         // cond(0) + 128 causal chunks

#define NORMALIZER 0.35355339059327373f  // 64^-0.25
#define DIAGC      0.0625f               // 0.5 * normalizer^2
#define RATIO      0.0625f               // 256^-0.5
#define EPSK       1e-4f
#define EPSC       1e-6f

// ---------------- scratch (static device globals; allocation-free) -----------
__device__ float g_QP[(size_t)BHN * NSEQ * MDIM];            // 64 MB  (qp final)
__device__ float g_KP[(size_t)BHN * NSEQ * MDIM];            // 64 MB  (dash_k - diag)
__device__ unsigned g_kmax;
__device__ float g_Lk  [(size_t)BHN * NSLOT * MDIM];
__device__ float g_Lctx[(size_t)BHN * NSLOT * MDIM * EDIM];  // 135 MB

__device__ __forceinline__ unsigned ford(float f) {
    unsigned u = __float_as_uint(f);
    return (u & 0x80000000u) ? ~u : (u | 0x80000000u);
}
__device__ __forceinline__ float fuord(unsigned u) {
    return (u & 0x80000000u) ? __uint_as_float(u ^ 0x80000000u)
                             : __uint_as_float(~u);
}

__global__ void init_kernel() { g_kmax = 0u; }

// ---------------- feature map:  dash = norm * (X @ projT) --------------------
template <bool IS_Q>
__global__ __launch_bounds__(256) void feat_kernel(const float* __restrict__ data,
                                                   const float* __restrict__ proj) {
    __shared__ float q_s[16 * 68];
    __shared__ float red[8 * 16];
    __shared__ float diag_s[16];
    __shared__ float rmax_s[16];

    const int tid  = threadIdx.x;
    const int lane = tid & 31, wid = tid >> 5;
    const size_t row0 = (size_t)blockIdx.x * 16;

    float4 p[16];
#pragma unroll
    for (int d4 = 0; d4 < 16; d4++)
        p[d4] = *(const float4*)&proj[tid * 64 + d4 * 4];

    for (int idx = tid; idx < 16 * 64; idx += 256) {
        int r = idx >> 6, dd = idx & 63;
        q_s[r * 68 + dd] = data[(row0 + r) * 64 + dd];
    }
    __syncthreads();

    if (tid < 16) {
        float s = 0.f;
        for (int dd = 0; dd < 64; dd++) { float x = q_s[tid * 68 + dd]; s += x * x; }
        diag_s[tid] = s * DIAGC;
    }
    __syncthreads();

    float acc[16];
#pragma unroll
    for (int r = 0; r < 16; r++) acc[r] = 0.f;

#pragma unroll
    for (int d4 = 0; d4 < 16; d4++) {
#pragma unroll
        for (int r = 0; r < 16; r++) {
            float4 qv = *(const float4*)&q_s[r * 68 + d4 * 4];   // LDS.128 broadcast
            acc[r] += qv.x * p[d4].x + qv.y * p[d4].y + qv.z * p[d4].z + qv.w * p[d4].w;
        }
    }
#pragma unroll
    for (int r = 0; r < 16; r++) acc[r] *= NORMALIZER;

    if (IS_Q) {
#pragma unroll
        for (int r = 0; r < 16; r++) {
            float v = acc[r];
            for (int off = 16; off; off >>= 1)
                v = fmaxf(v, __shfl_xor_sync(0xffffffffu, v, off));
            if (lane == 0) red[wid * 16 + r] = v;
        }
        __syncthreads();
        if (tid < 16) {
            float m = red[tid];
            for (int w = 1; w < 8; w++) m = fmaxf(m, red[w * 16 + tid]);
            rmax_s[tid] = m;
        }
        __syncthreads();
#pragma unroll
        for (int r = 0; r < 16; r++)
            g_QP[(row0 + r) * 256 + tid] =
                RATIO * (__expf(acc[r] - diag_s[r] - rmax_s[r]) + EPSK);
    } else {
        float bm = acc[0];
#pragma unroll
        for (int r = 1; r < 16; r++) bm = fmaxf(bm, acc[r]);
        for (int off = 16; off; off >>= 1)
            bm = fmaxf(bm, __shfl_xor_sync(0xffffffffu, bm, off));
        if (lane == 0) red[wid] = bm;
        __syncthreads();
        if (tid == 0) {
            float m = red[0];
            for (int w = 1; w < 8; w++) m = fmaxf(m, red[w]);
            atomicMax(&g_kmax, ford(m));
        }
#pragma unroll
        for (int r = 0; r < 16; r++)
            g_KP[(row0 + r) * 256 + tid] = acc[r] - diag_s[r];   // store dash-diag
    }
}

// ---------------- per-chunk local sums (exp applied on the fly) --------------
__global__ __launch_bounds__(256) void chunk_sums_kernel(const float* __restrict__ v) {
    __shared__ float kp_s[32 * 256];   // 32 KB
    __shared__ float v_s[32 * 64];     // 8 KB
    const int tid = threadIdx.x;
    const int slot = blockIdx.x, bh = blockIdx.y;
    const int t0  = slot ? (LCOND + (slot - 1) * LCH) : 0;
    const int len = slot ? LCH : LCOND;
    const float gmax = fuord(g_kmax);

    float acc[64];
#pragma unroll
    for (int e = 0; e < 64; e++) acc[e] = 0.f;
    float sk = 0.f;

    for (int base = 0; base < len; base += 32) {
        int tl = min(32, len - base);
        __syncthreads();
        for (int idx = tid; idx < tl * 256; idx += 256)
            kp_s[idx] = RATIO * (__expf(g_KP[((size_t)bh * NSEQ + t0 + base) * 256 + idx] - gmax) + EPSK);
        for (int idx = tid; idx < tl * 64; idx += 256)
            v_s[idx] = v[((size_t)bh * NSEQ + t0 + base) * 64 + idx];
        __syncthreads();
        for (int tt = 0; tt < tl; tt++) {
            float km = kp_s[tt * 256 + tid];
            sk += km;
#pragma unroll
            for (int e4 = 0; e4 < 16; e4++) {
                float4 vv = *(const float4*)&v_s[tt * 64 + e4 * 4];
                acc[e4 * 4 + 0] += km * vv.x;
                acc[e4 * 4 + 1] += km * vv.y;
                acc[e4 * 4 + 2] += km * vv.z;
                acc[e4 * 4 + 3] += km * vv.w;
            }
        }
    }
    g_Lk[((size_t)bh * NSLOT + slot) * 256 + tid] = sk;
    size_t ob = (((size_t)bh * NSLOT + slot) * 256 + tid) * 64;
#pragma unroll
    for (int e4 = 0; e4 < 16; e4++)
        *(float4*)&g_Lctx[ob + e4 * 4] =
            make_float4(acc[e4 * 4], acc[e4 * 4 + 1], acc[e4 * 4 + 2], acc[e4 * 4 + 3]);
}

// ---------------- exclusive prefix over chunks (batched loads, MLP=8) --------
__global__ __launch_bounds__(256) void prefix_kernel() {
    const int g = blockIdx.x * 256 + threadIdx.x;   // 0..16639
    const int bh = blockIdx.y;
    float* buf; size_t base, stride;
    if (g < 256) { buf = g_Lk;   base = (size_t)bh * NSLOT * 256 + g;            stride = 256; }
    else         { buf = g_Lctx; base = (size_t)bh * NSLOT * 16384 + (g - 256);  stride = 16384; }

    float acc = buf[base];
#pragma unroll 1
    for (int c0 = 1; c0 < NSLOT; c0 += 8) {     // 128 = 16 groups of 8
        float t[8];
#pragma unroll
        for (int u = 0; u < 8; u++)
            t[u] = buf[base + (size_t)(c0 + u) * stride];   // 8 independent loads
#pragma unroll
        for (int u = 0; u < 8; u++) {
            float nxt = t[u];
            buf[base + (size_t)(c0 + u) * stride] = acc;    // exclusive
            acc += nxt;
        }
    }
}

// ---------------- conditioning-prefix output ---------------------------------
__global__ __launch_bounds__(128) void cond_out_kernel(float* __restrict__ out) {
    __shared__ float sden[4];
    const int tid = threadIdx.x;
    const int rl = tid >> 6, e = tid & 63;
    const int lane = tid & 31, wid = tid >> 5;
    const int bh = blockIdx.y;
    const int row = blockIdx.x * 2 + rl;
    const float* qrow = g_QP + ((size_t)bh * NSEQ + row) * 256;
    const float* lk0  = g_Lk   + (size_t)bh * NSLOT * 256;
    const float* ctx0 = g_Lctx + (size_t)bh * NSLOT * 16384;

    float p = 0.f;
    for (int m = e; m < 256; m += 64) p += qrow[m] * lk0[m];
    for (int off = 16; off; off >>= 1) p += __shfl_xor_sync(0xffffffffu, p, off);
    if (lane == 0) sden[wid] = p;
    __syncthreads();
    float den = sden[rl * 2] + sden[rl * 2 + 1];

    float acc = 0.f;
    for (int m4 = 0; m4 < 64; m4++) {
        float4 q4 = *(const float4*)&qrow[m4 * 4];
        acc += q4.x * ctx0[(m4 * 4 + 0) * 64 + e] + q4.y * ctx0[(m4 * 4 + 1) * 64 + e]
             + q4.z * ctx0[(m4 * 4 + 2) * 64 + e] + q4.w * ctx0[(m4 * 4 + 3) * 64 + e];
    }
    out[((size_t)bh * NSEQ + row) * 64 + e] = acc / den;
}

// ---------------- causal chunk output (exp on the fly for K) -----------------
#define QPAD 132
#define KPAD 133

__global__ __launch_bounds__(256) void causal_out_kernel(const float* __restrict__ v,
                                                         float* __restrict__ out) {
    __shared__ float q_s[LCH * QPAD];   // 15.84 KB
    __shared__ float k_s[LCH * KPAD];   // 15.96 KB
    __shared__ float v_s[LCH * 64];     // 7.5 KB
    __shared__ float A[32 * 32];
    __shared__ float ck[256];
    __shared__ float dinv[32];

    const int tid = threadIdx.x, lane = tid & 31, w = tid >> 5;
    const int ci = blockIdx.x, bh = blockIdx.y;
    const int t0 = LCOND + ci * LCH;
    const int slot = ci + 1;
    const float gmax = fuord(g_kmax);

    const float* qb = g_QP + ((size_t)bh * NSEQ + t0) * 256;
    const float* kb = g_KP + ((size_t)bh * NSEQ + t0) * 256;
    const float* vb = v    + ((size_t)bh * NSEQ + t0) * 64;
    const float* ctxc = g_Lctx + ((size_t)bh * NSLOT + slot) * 16384;

    for (int idx = tid; idx < LCH * 64; idx += 256) v_s[idx] = vb[idx];
    ck[tid] = g_Lk[((size_t)bh * NSLOT + slot) * 256 + tid];

    float a0 = 0.f, a1 = 0.f, a2 = 0.f, a3 = 0.f;
    float pden[4] = {0.f, 0.f, 0.f, 0.f};
    const int g = tid >> 6, e = tid & 63;
    float acc[8];
#pragma unroll
    for (int r = 0; r < 8; r++) acc[r] = 0.f;

    const int klane = (lane < LCH) ? lane : (LCH - 1);

    for (int mt = 0; mt < 2; mt++) {
        const int m0 = mt * 128;
        __syncthreads();
        for (int idx = tid; idx < LCH * 128; idx += 256) {
            int i = idx >> 7, ml = idx & 127;
            q_s[i * QPAD + ml] = qb[i * 256 + m0 + ml];
            k_s[i * KPAD + ml] = RATIO * (__expf(kb[i * 256 + m0 + ml] - gmax) + EPSK);
        }
        __syncthreads();

        {
            const float* krow = &k_s[klane * KPAD];
            const int iA = w, iB = w + 8, iC = w + 16, iD = (w + 24 < LCH) ? w + 24 : 0;
#pragma unroll 8
            for (int m4 = 0; m4 < 32; m4++) {
                float k0 = krow[m4 * 4 + 0], k1 = krow[m4 * 4 + 1];
                float k2 = krow[m4 * 4 + 2], k3 = krow[m4 * 4 + 3];
                float4 qA = *(const float4*)&q_s[iA * QPAD + m4 * 4];
                float4 qB = *(const float4*)&q_s[iB * QPAD + m4 * 4];
                float4 qC = *(const float4*)&q_s[iC * QPAD + m4 * 4];
                float4 qD = *(const float4*)&q_s[iD * QPAD + m4 * 4];
                a0 += qA.x * k0 + qA.y * k1 + qA.z * k2 + qA.w * k3;
                a1 += qB.x * k0 + qB.y * k1 + qB.z * k2 + qB.w * k3;
                a2 += qC.x * k0 + qC.y * k1 + qC.z * k2 + qC.w * k3;
                a3 += qD.x * k0 + qD.y * k1 + qD.z * k2 + qD.w * k3;
            }
        }

#pragma unroll
        for (int r = 0; r < 4; r++) {
            int i = w + 8 * r;
            if (i < LCH) {
                float p = 0.f;
                for (int ml = lane; ml < 128; ml += 32)
                    p += q_s[i * QPAD + ml] * (ck[m0 + ml] + EPSC);
                pden[r] += p;
            }
        }

        for (int m4 = 0; m4 < 32; m4++) {
            float c0 = ctxc[(m0 + m4 * 4 + 0) * 64 + e];
            float c1 = ctxc[(m0 + m4 * 4 + 1) * 64 + e];
            float c2 = ctxc[(m0 + m4 * 4 + 2) * 64 + e];
            float c3 = ctxc[(m0 + m4 * 4 + 3) * 64 + e];
#pragma unroll
            for (int r = 0; r < 8; r++) {
                int i = g + 4 * r;
                if (i < LCH) {
                    float4 q4 = *(const float4*)&q_s[i * QPAD + m4 * 4];
                    acc[r] += q4.x * c0 + q4.y * c1 + q4.z * c2 + q4.w * c3;
                }
            }
        }
    }

    if (lane < LCH) {
        A[(w     ) * 32 + lane] = a0;
        A[(w +  8) * 32 + lane] = a1;
        A[(w + 16) * 32 + lane] = a2;
        if (w + 24 < LCH) A[(w + 24) * 32 + lane] = a3;
    }
    __syncthreads();

#pragma unroll
    for (int r = 0; r < 4; r++) {
        int i = w + 8 * r;
        if (i < LCH) {
            float p = pden[r];
            if (lane <= i) p += A[i * 32 + lane];
            for (int off = 16; off; off >>= 1) p += __shfl_xor_sync(0xffffffffu, p, off);
            if (lane == 0) dinv[i] = 1.f / p;
        }
    }
    __syncthreads();

#pragma unroll
    for (int r = 0; r < 8; r++) {
        int i = g + 4 * r;
        if (i >= LCH) continue;
        float o = acc[r];
        for (int j = 0; j <= i; j++) o += A[i * 32 + j] * v_s[j * 64 + e];
        out[((size_t)bh * NSEQ + t0 + i) * 64 + e] = o * dinv[i];
    }
}

// ---------------- launch ------------------------------------------------------
extern "C" void kernel_launch(void* const* d_in, const int* in_sizes, int n_in,
                              void* d_out, int out_size) {
    (void)in_sizes; (void)n_in; (void)out_size;
    const float* q    = (const float*)d_in[0];
    const float* k    = (const float*)d_in[1];
    const float* v    = (const float*)d_in[2];
    const float* proj = (const float*)d_in[3];
    float* out = (float*)d_out;

    init_kernel<<<1, 1>>>();
    feat_kernel<false><<<4096, 256>>>(k, proj);
    feat_kernel<true> <<<4096, 256>>>(q, proj);
    chunk_sums_kernel <<<dim3(NSLOT, BHN), 256>>>(v);
    prefix_kernel     <<<dim3(65, BHN), 256>>>();
    cond_out_kernel   <<<dim3(128, BHN), 128>>>(out);
    causal_out_kernel <<<dim3(NCHUNK, BHN), 256>>>(v, out);
}

// round 5
// speedup vs baseline: 1.5141x; 1.0171x over previous
#include <cuda_runtime.h>
#include <math.h>

// Problem constants (b=2,h=8,n=4096,d=64,m=256)
#define BHN   16
#define NSEQ  4096
#define DDIM  64
#define MDIM  256
#define LCOND 256
#define NCHUNK 128
#define LCH   30
#define EDIM  64
#define NSLOT 129         // cond(0) + 128 causal chunks

#define NORMALIZER 0.35355339059327373f  // 64^-0.25
#define DIAGC      0.0625f               // 0.5 * normalizer^2
#define RATIO      0.0625f               // 256^-0.5
#define EPSK       1e-4f
#define EPSC       1e-6f

// ---------------- scratch (static device globals; allocation-free) -----------
__device__ float g_QP[(size_t)BHN * NSEQ * MDIM];            // 64 MB  (qp final)
__device__ float g_KP[(size_t)BHN * NSEQ * MDIM];            // 64 MB  (dash_k - diag)
__device__ unsigned g_kmax;
__device__ float g_Lk  [(size_t)BHN * NSLOT * MDIM];
__device__ float g_Lctx[(size_t)BHN * NSLOT * MDIM * EDIM];  // 135 MB

__device__ __forceinline__ unsigned ford(float f) {
    unsigned u = __float_as_uint(f);
    return (u & 0x80000000u) ? ~u : (u | 0x80000000u);
}
__device__ __forceinline__ float fuord(unsigned u) {
    return (u & 0x80000000u) ? __uint_as_float(u ^ 0x80000000u)
                             : __uint_as_float(~u);
}

__global__ void init_kernel() { g_kmax = 0u; }

// ---------------- feature map:  dash = norm * (X @ projT) --------------------
template <bool IS_Q>
__global__ __launch_bounds__(256) void feat_kernel(const float* __restrict__ data,
                                                   const float* __restrict__ proj) {
    __shared__ float q_s[16 * 68];
    __shared__ float red[8 * 16];
    __shared__ float diag_s[16];
    __shared__ float rmax_s[16];

    const int tid  = threadIdx.x;
    const int lane = tid & 31, wid = tid >> 5;
    const size_t row0 = (size_t)blockIdx.x * 16;

    float4 p[16];
#pragma unroll
    for (int d4 = 0; d4 < 16; d4++)
        p[d4] = *(const float4*)&proj[tid * 64 + d4 * 4];

    for (int idx = tid; idx < 16 * 64; idx += 256) {
        int r = idx >> 6, dd = idx & 63;
        q_s[r * 68 + dd] = data[(row0 + r) * 64 + dd];
    }
    __syncthreads();

    if (tid < 16) {
        float s = 0.f;
        for (int dd = 0; dd < 64; dd++) { float x = q_s[tid * 68 + dd]; s += x * x; }
        diag_s[tid] = s * DIAGC;
    }
    __syncthreads();

    float acc[16];
#pragma unroll
    for (int r = 0; r < 16; r++) acc[r] = 0.f;

#pragma unroll
    for (int d4 = 0; d4 < 16; d4++) {
#pragma unroll
        for (int r = 0; r < 16; r++) {
            float4 qv = *(const float4*)&q_s[r * 68 + d4 * 4];   // LDS.128 broadcast
            acc[r] += qv.x * p[d4].x + qv.y * p[d4].y + qv.z * p[d4].z + qv.w * p[d4].w;
        }
    }
#pragma unroll
    for (int r = 0; r < 16; r++) acc[r] *= NORMALIZER;

    if (IS_Q) {
#pragma unroll
        for (int r = 0; r < 16; r++) {
            float v = acc[r];
            for (int off = 16; off; off >>= 1)
                v = fmaxf(v, __shfl_xor_sync(0xffffffffu, v, off));
            if (lane == 0) red[wid * 16 + r] = v;
        }
        __syncthreads();
        if (tid < 16) {
            float m = red[tid];
            for (int w = 1; w < 8; w++) m = fmaxf(m, red[w * 16 + tid]);
            rmax_s[tid] = m;
        }
        __syncthreads();
#pragma unroll
        for (int r = 0; r < 16; r++)
            g_QP[(row0 + r) * 256 + tid] =
                RATIO * (__expf(acc[r] - diag_s[r] - rmax_s[r]) + EPSK);
    } else {
        float bm = acc[0];
#pragma unroll
        for (int r = 1; r < 16; r++) bm = fmaxf(bm, acc[r]);
        for (int off = 16; off; off >>= 1)
            bm = fmaxf(bm, __shfl_xor_sync(0xffffffffu, bm, off));
        if (lane == 0) red[wid] = bm;
        __syncthreads();
        if (tid == 0) {
            float m = red[0];
            for (int w = 1; w < 8; w++) m = fmaxf(m, red[w]);
            atomicMax(&g_kmax, ford(m));
        }
#pragma unroll
        for (int r = 0; r < 16; r++)
            g_KP[(row0 + r) * 256 + tid] = acc[r] - diag_s[r];   // store dash-diag
    }
}

// ---------------- per-chunk local sums (1024 thr: 256 m x 4 e-groups) --------
__global__ __launch_bounds__(1024) void chunk_sums_kernel(const float* __restrict__ v) {
    __shared__ float kp_s[32 * 256];   // 32 KB
    __shared__ float v_s[32 * 64];     // 8 KB
    const int tid = threadIdx.x;
    const int m = tid & 255, eg = tid >> 8;        // eg uniform per warp
    const int slot = blockIdx.x, bh = blockIdx.y;
    const int t0  = slot ? (LCOND + (slot - 1) * LCH) : 0;
    const int len = slot ? LCH : LCOND;
    const float gmax = fuord(g_kmax);

    float acc[16];
#pragma unroll
    for (int e = 0; e < 16; e++) acc[e] = 0.f;
    float sk = 0.f;

    for (int base = 0; base < len; base += 32) {
        int tl = min(32, len - base);
        __syncthreads();
        for (int idx = tid; idx < tl * 256; idx += 1024)
            kp_s[idx] = RATIO * (__expf(g_KP[((size_t)bh * NSEQ + t0 + base) * 256 + idx] - gmax) + EPSK);
        for (int idx = tid; idx < tl * 64; idx += 1024)
            v_s[idx] = v[((size_t)bh * NSEQ + t0 + base) * 64 + idx];
        __syncthreads();
        for (int tt = 0; tt < tl; tt++) {
            float km = kp_s[tt * 256 + m];         // stride-1 across lanes
            if (eg == 0) sk += km;
#pragma unroll
            for (int c = 0; c < 4; c++) {
                float4 vv = *(const float4*)&v_s[tt * 64 + eg * 16 + c * 4];  // warp broadcast
                acc[c * 4 + 0] += km * vv.x;
                acc[c * 4 + 1] += km * vv.y;
                acc[c * 4 + 2] += km * vv.z;
                acc[c * 4 + 3] += km * vv.w;
            }
        }
    }
    if (eg == 0) g_Lk[((size_t)bh * NSLOT + slot) * 256 + m] = sk;
    size_t ob = (((size_t)bh * NSLOT + slot) * 256 + m) * 64 + eg * 16;
#pragma unroll
    for (int c = 0; c < 4; c++)
        *(float4*)&g_Lctx[ob + c * 4] =
            make_float4(acc[c * 4], acc[c * 4 + 1], acc[c * 4 + 2], acc[c * 4 + 3]);
}

// ---------------- exclusive prefix over chunks (float4 + MLP=8) --------------
__global__ __launch_bounds__(256) void prefix_kernel() {
    const int g = blockIdx.x * 256 + threadIdx.x;   // 0..4351
    const int bh = blockIdx.y;

    if (g < 256) {
        size_t base = (size_t)bh * NSLOT * 256 + g;
        float acc = g_Lk[base];
#pragma unroll 1
        for (int c0 = 1; c0 < NSLOT; c0 += 8) {
            float t[8];
#pragma unroll
            for (int u = 0; u < 8; u++)
                t[u] = g_Lk[base + (size_t)(c0 + u) * 256];
#pragma unroll
            for (int u = 0; u < 8; u++) {
                float nxt = t[u];
                g_Lk[base + (size_t)(c0 + u) * 256] = acc;
                acc += nxt;
            }
        }
    } else {
        size_t base = (size_t)bh * NSLOT * 16384 + (size_t)(g - 256) * 4;
        float4 acc = *(float4*)&g_Lctx[base];
#pragma unroll 1
        for (int c0 = 1; c0 < NSLOT; c0 += 8) {
            float4 t[8];
#pragma unroll
            for (int u = 0; u < 8; u++)
                t[u] = *(float4*)&g_Lctx[base + (size_t)(c0 + u) * 16384];
#pragma unroll
            for (int u = 0; u < 8; u++) {
                float4 nxt = t[u];
                *(float4*)&g_Lctx[base + (size_t)(c0 + u) * 16384] = acc;
                acc.x += nxt.x; acc.y += nxt.y; acc.z += nxt.z; acc.w += nxt.w;
            }
        }
    }
}

// ---------------- conditioning-prefix output ---------------------------------
__global__ __launch_bounds__(128) void cond_out_kernel(float* __restrict__ out) {
    __shared__ float sden[4];
    const int tid = threadIdx.x;
    const int rl = tid >> 6, e = tid & 63;
    const int lane = tid & 31, wid = tid >> 5;
    const int bh = blockIdx.y;
    const int row = blockIdx.x * 2 + rl;
    const float* qrow = g_QP + ((size_t)bh * NSEQ + row) * 256;
    const float* lk0  = g_Lk   + (size_t)bh * NSLOT * 256;
    const float* ctx0 = g_Lctx + (size_t)bh * NSLOT * 16384;

    float p = 0.f;
    for (int m = e; m < 256; m += 64) p += qrow[m] * lk0[m];
    for (int off = 16; off; off >>= 1) p += __shfl_xor_sync(0xffffffffu, p, off);
    if (lane == 0) sden[wid] = p;
    __syncthreads();
    float den = sden[rl * 2] + sden[rl * 2 + 1];

    float acc = 0.f;
    for (int m4 = 0; m4 < 64; m4++) {
        float4 q4 = *(const float4*)&qrow[m4 * 4];
        acc += q4.x * ctx0[(m4 * 4 + 0) * 64 + e] + q4.y * ctx0[(m4 * 4 + 1) * 64 + e]
             + q4.z * ctx0[(m4 * 4 + 2) * 64 + e] + q4.w * ctx0[(m4 * 4 + 3) * 64 + e];
    }
    out[((size_t)bh * NSEQ + row) * 64 + e] = acc / den;
}

// ---------------- causal chunk output (exp on the fly for K) -----------------
#define QPAD 132
#define KPAD 133

__global__ __launch_bounds__(256) void causal_out_kernel(const float* __restrict__ v,
                                                         float* __restrict__ out) {
    __shared__ float q_s[LCH * QPAD];   // 15.84 KB
    __shared__ float k_s[LCH * KPAD];   // 15.96 KB
    __shared__ float v_s[LCH * 64];     // 7.5 KB
    __shared__ float A[32 * 32];
    __shared__ float ck[256];
    __shared__ float dinv[32];

    const int tid = threadIdx.x, lane = tid & 31, w = tid >> 5;
    const int ci = blockIdx.x, bh = blockIdx.y;
    const int t0 = LCOND + ci * LCH;
    const int slot = ci + 1;
    const float gmax = fuord(g_kmax);

    const float* qb = g_QP + ((size_t)bh * NSEQ + t0) * 256;
    const float* kb = g_KP + ((size_t)bh * NSEQ + t0) * 256;
    const float* vb = v    + ((size_t)bh * NSEQ + t0) * 64;
    const float* ctxc = g_Lctx + ((size_t)bh * NSLOT + slot) * 16384;

    for (int idx = tid; idx < LCH * 64; idx += 256) v_s[idx] = vb[idx];
    ck[tid] = g_Lk[((size_t)bh * NSLOT + slot) * 256 + tid];

    float a0 = 0.f, a1 = 0.f, a2 = 0.f, a3 = 0.f;
    float pden[4] = {0.f, 0.f, 0.f, 0.f};
    const int g = tid >> 6, e = tid & 63;
    float acc[8];
#pragma unroll
    for (int r = 0; r < 8; r++) acc[r] = 0.f;

    const int klane = (lane < LCH) ? lane : (LCH - 1);

    for (int mt = 0; mt < 2; mt++) {
        const int m0 = mt * 128;
        __syncthreads();
        for (int idx = tid; idx < LCH * 128; idx += 256) {
            int i = idx >> 7, ml = idx & 127;
            q_s[i * QPAD + ml] = qb[i * 256 + m0 + ml];
            k_s[i * KPAD + ml] = RATIO * (__expf(kb[i * 256 + m0 + ml] - gmax) + EPSK);
        }
        __syncthreads();

        {
            const float* krow = &k_s[klane * KPAD];
            const int iA = w, iB = w + 8, iC = w + 16, iD = (w + 24 < LCH) ? w + 24 : 0;
#pragma unroll 8
            for (int m4 = 0; m4 < 32; m4++) {
                float k0 = krow[m4 * 4 + 0], k1 = krow[m4 * 4 + 1];
                float k2 = krow[m4 * 4 + 2], k3 = krow[m4 * 4 + 3];
                float4 qA = *(const float4*)&q_s[iA * QPAD + m4 * 4];
                float4 qB = *(const float4*)&q_s[iB * QPAD + m4 * 4];
                float4 qC = *(const float4*)&q_s[iC * QPAD + m4 * 4];
                float4 qD = *(const float4*)&q_s[iD * QPAD + m4 * 4];
                a0 += qA.x * k0 + qA.y * k1 + qA.z * k2 + qA.w * k3;
                a1 += qB.x * k0 + qB.y * k1 + qB.z * k2 + qB.w * k3;
                a2 += qC.x * k0 + qC.y * k1 + qC.z * k2 + qC.w * k3;
                a3 += qD.x * k0 + qD.y * k1 + qD.z * k2 + qD.w * k3;
            }
        }

#pragma unroll
        for (int r = 0; r < 4; r++) {
            int i = w + 8 * r;
            if (i < LCH) {
                float p = 0.f;
                for (int ml = lane; ml < 128; ml += 32)
                    p += q_s[i * QPAD + ml] * (ck[m0 + ml] + EPSC);
                pden[r] += p;
            }
        }

        for (int m4 = 0; m4 < 32; m4++) {
            float c0 = ctxc[(m0 + m4 * 4 + 0) * 64 + e];
            float c1 = ctxc[(m0 + m4 * 4 + 1) * 64 + e];
            float c2 = ctxc[(m0 + m4 * 4 + 2) * 64 + e];
            float c3 = ctxc[(m0 + m4 * 4 + 3) * 64 + e];
#pragma unroll
            for (int r = 0; r < 8; r++) {
                int i = g + 4 * r;
                if (i < LCH) {
                    float4 q4 = *(const float4*)&q_s[i * QPAD + m4 * 4];
                    acc[r] += q4.x * c0 + q4.y * c1 + q4.z * c2 + q4.w * c3;
                }
            }
        }
    }

    if (lane < LCH) {
        A[(w     ) * 32 + lane] = a0;
        A[(w +  8) * 32 + lane] = a1;
        A[(w + 16) * 32 + lane] = a2;
        if (w + 24 < LCH) A[(w + 24) * 32 + lane] = a3;
    }
    __syncthreads();

#pragma unroll
    for (int r = 0; r < 4; r++) {
        int i = w + 8 * r;
        if (i < LCH) {
            float p = pden[r];
            if (lane <= i) p += A[i * 32 + lane];
            for (int off = 16; off; off >>= 1) p += __shfl_xor_sync(0xffffffffu, p, off);
            if (lane == 0) dinv[i] = 1.f / p;
        }
    }
    __syncthreads();

#pragma unroll
    for (int r = 0; r < 8; r++) {
        int i = g + 4 * r;
        if (i >= LCH) continue;
        float o = acc[r];
        for (int j = 0; j <= i; j++) o += A[i * 32 + j] * v_s[j * 64 + e];
        out[((size_t)bh * NSEQ + t0 + i) * 64 + e] = o * dinv[i];
    }
}

// ---------------- launch ------------------------------------------------------
extern "C" void kernel_launch(void* const* d_in, const int* in_sizes, int n_in,
                              void* d_out, int out_size) {
    (void)in_sizes; (void)n_in; (void)out_size;
    const float* q    = (const float*)d_in[0];
    const float* k    = (const float*)d_in[1];
    const float* v    = (const float*)d_in[2];
    const float* proj = (const float*)d_in[3];
    float* out = (float*)d_out;

    init_kernel<<<1, 1>>>();
    feat_kernel<false><<<4096, 256>>>(k, proj);
    feat_kernel<true> <<<4096, 256>>>(q, proj);
    chunk_sums_kernel <<<dim3(NSLOT, BHN), 1024>>>(v);
    prefix_kernel     <<<dim3(17, BHN), 256>>>();
    cond_out_kernel   <<<dim3(128, BHN), 128>>>(out);
    causal_out_kernel <<<dim3(NCHUNK, BHN), 256>>>(v, out);
}